// round 14
// baseline (speedup 1.0000x reference)
#include <cuda_runtime.h>
#include <math.h>

#define VV (48*48*48)          // 110592 voxels
#define EPSF 1e-5f

// ---------------- scratch (static device globals; no allocation) ----------------
__device__ float4 g_xl[(size_t)VV * 4];     // x as [z][y][c4][x] float4   (7 MB)
__device__ float  g_off[(size_t)18 * VV];   // offset conv out (18 ch)    (8 MB)
__device__ float  g_pre[(size_t)32 * VV];   // pre-groupnorm conv out     (14 MB)
__device__ double g_part[8 * 96 * 2];       // per-(group, block) partials
__device__ float  g_mean[8], g_rstd[8];
__device__ unsigned int g_done;             // gsum completion counter

__global__ void init_k() {
    if (threadIdx.x == 0) g_done = 0u;
    if (threadIdx.x < 8) { g_mean[threadIdx.x] = 0.f; g_rstd[threadIdx.x] = 0.f; }
}

// ---------------- transpose x -> [z][y][c4][x] float4 ----------------
__global__ void transpose_k(const float* __restrict__ x) {
    int vox = blockIdx.x * 128 + threadIdx.x;
    if (vox >= VV) return;
    float t[16];
#pragma unroll
    for (int ci = 0; ci < 16; ci++) t[ci] = x[(size_t)ci * VV + vox];
    int hx = vox % 48;
    int r  = vox / 48;
    int wy = r % 48;
    int dz = r / 48;
    int base = ((dz * 48 + wy) * 4) * 48 + hx;
    g_xl[base      ] = make_float4(t[0],  t[1],  t[2],  t[3]);
    g_xl[base + 48 ] = make_float4(t[4],  t[5],  t[6],  t[7]);
    g_xl[base + 96 ] = make_float4(t[8],  t[9],  t[10], t[11]);
    g_xl[base + 144] = make_float4(t[12], t[13], t[14], t[15]);
}

// ---------------- offset conv: 4 d x 2 h per thread, 3 co ----------------------
// R14: each thread produces 24 outputs (3co x 4d x 2h). The 4-wide h tap window
// loads as 2x LDS.64 (h0 even, rows 200B -> 8B aligned). Per (ci,dy) iteration:
// 12 LDS.64 + 27 w-LDS feed 216 FMA -> per-output LDS halves vs R13.
__global__ __launch_bounds__(144) void offset_conv_k(const float* __restrict__ x,
                              const float* __restrict__ ow,
                              const float* __restrict__ ob,
                              const float* __restrict__ bn_g,
                              const float* __restrict__ bn_b,
                              const float* __restrict__ bn_m,
                              const float* __restrict__ bn_v) {
    __shared__ float sx[8][6][3][50];      // 28.8KB
    __shared__ float sw[18 * 8 * 3 * 10];  // 17.3KB, [co][ci][dy][dz*3+t pad 10]

    int w  = blockIdx.x, d0 = blockIdx.y * 4;
    int tid = threadIdx.y * 24 + threadIdx.x;   // 144 threads
    int h0  = threadIdx.x * 2;
    int co0 = threadIdx.y * 3;

    float acc[3][4][2];
#pragma unroll
    for (int j = 0; j < 3; j++)
#pragma unroll
        for (int i = 0; i < 4; i++) { acc[j][i][0] = 0.f; acc[j][i][1] = 0.f; }

    for (int p = 0; p < 2; p++) {
        __syncthreads();
        for (int e = tid; e < 7200; e += 144) {
            int ci = e / 900, r = e % 900;
            int pl = r / 150; r %= 150;
            int dy = r / 50, hh = r % 50;
            int z = d0 + pl - 1, y = w + dy - 1, xx = hh - 1;
            float v = 0.f;
            if ((unsigned)z < 48u && (unsigned)y < 48u && (unsigned)xx < 48u)
                v = x[(size_t)(ci + 8 * p) * VV + ((size_t)z * 48 + y) * 48 + xx];
            sx[ci][pl][dy][hh] = v;
        }
        for (int e = tid; e < 3888; e += 144) {
            int co = e / 216, r = e % 216;
            int ci = r / 27, tt = r % 27;
            int dz = tt / 9, rem = tt % 9;
            int dy = rem / 3, t = rem % 3;
            sw[(((co * 8 + ci) * 3) + dy) * 10 + dz * 3 + t] =
                ow[(size_t)(co * 16 + ci + 8 * p) * 27 + tt];
        }
        __syncthreads();

#pragma unroll
        for (int ci = 0; ci < 8; ci++) {
#pragma unroll
            for (int dy = 0; dy < 3; dy++) {
                float v[6][4];
#pragma unroll
                for (int pl = 0; pl < 6; pl++) {
                    float2 a = *reinterpret_cast<const float2*>(&sx[ci][pl][dy][h0]);
                    float2 b = *reinterpret_cast<const float2*>(&sx[ci][pl][dy][h0 + 2]);
                    v[pl][0] = a.x; v[pl][1] = a.y; v[pl][2] = b.x; v[pl][3] = b.y;
                }
#pragma unroll
                for (int j = 0; j < 3; j++) {
                    const float* wp = &sw[((((co0 + j) * 8 + ci) * 3) + dy) * 10];
#pragma unroll
                    for (int dz = 0; dz < 3; dz++) {
#pragma unroll
                        for (int t = 0; t < 3; t++) {
                            float wv = wp[dz * 3 + t];
#pragma unroll
                            for (int i = 0; i < 4; i++) {
                                acc[j][i][0] += v[i + dz][t]     * wv;
                                acc[j][i][1] += v[i + dz][t + 1] * wv;
                            }
                        }
                    }
                }
            }
        }
    }

#pragma unroll
    for (int j = 0; j < 3; j++) {
        int c = co0 + j;
        float al = bn_g[c] * rsqrtf(bn_v[c] + EPSF);
        float sh = ob[c] - bn_m[c];
#pragma unroll
        for (int i = 0; i < 4; i++) {
#pragma unroll
            for (int hh = 0; hh < 2; hh++) {
                int vo = (((size_t)(d0 + i) * 48 + w) * 48) + h0 + hh;
                g_off[(size_t)c * VV + vo] = tanhf((acc[j][i][hh] + sh) * al + bn_b[c]);
            }
        }
    }
}

// ---------------- dsc: cumsum + 4-corner gather + (1,1,9) conv, 2 vox/thread ----
// (exact R11 configuration: 141 regs / 3 blocks/SM, 55us measured)
__global__ __launch_bounds__(128) void dsc_k(const float* __restrict__ dwt,
                                             const float* __restrict__ db) {
    __shared__ float s_dw[16 * 9 * 32];     // [ci][k][co]  18KB
    __shared__ float s_cz[9][256];          // 9KB
    __shared__ float s_cy[9][256];          // 9KB

    int tid = threadIdx.x;
    for (int e = tid; e < 4608; e += 128) {
        int co = e / 144, r = e % 144;
        int ci = r / 9, k = r % 9;
        s_dw[(ci * 9 + k) * 32 + co] = dwt[e];
    }

    int voxA = blockIdx.x * 256 + tid;      // 432 blocks * 256 vox = VV exactly

    for (int half = 0; half < 2; half++) {
        int vox = voxA + half * 128;
        int col = tid + half * 128;
        float o[9];
#pragma unroll
        for (int k = 0; k < 9; k++) o[k] = g_off[(size_t)k * VV + vox];
        float c3 = o[3], c2 = o[2] + c3, c1 = o[1] + c2, c0 = o[0] + c1;
        float c5 = o[5], c6 = o[6] + c5, c7 = o[7] + c6, c8 = o[8] + c7;
        s_cz[0][col] = c0; s_cz[1][col] = c1; s_cz[2][col] = c2; s_cz[3][col] = c3;
        s_cz[4][col] = 0.f;
        s_cz[5][col] = c5; s_cz[6][col] = c6; s_cz[7][col] = c7; s_cz[8][col] = c8;
#pragma unroll
        for (int k = 0; k < 9; k++) o[k] = g_off[(size_t)(9 + k) * VV + vox];
        c3 = o[3]; c2 = o[2] + c3; c1 = o[1] + c2; c0 = o[0] + c1;
        c5 = o[5]; c6 = o[6] + c5; c7 = o[7] + c6; c8 = o[8] + c7;
        s_cy[0][col] = c0; s_cy[1][col] = c1; s_cy[2][col] = c2; s_cy[3][col] = c3;
        s_cy[4][col] = 0.f;
        s_cy[5][col] = c5; s_cy[6][col] = c6; s_cy[7][col] = c7; s_cy[8][col] = c8;
    }
    __syncthreads();

    int voxB = voxA + 128;
    int hA = voxA % 48, tA = voxA / 48, wA = tA % 48, dA = tA / 48;
    int hB = voxB % 48, tB = voxB / 48, wB = tB % 48, dB = tB / 48;

    float accA[32], accB[32];
#pragma unroll
    for (int co = 0; co < 32; co++) { float b = db[co]; accA[co] = b; accB[co] = b; }

    for (int k = 0; k < 9; k++) {
        float zA = fminf(fmaxf((float)dA + s_cz[k][tid], 0.f), 47.f);
        float yA = fminf(fmaxf((float)wA + s_cy[k][tid], 0.f), 47.f);
        int xiA = max(0, min(hA + k - 4, 47));
        float wxA = (xiA == 47) ? 0.f : 1.f;
        int z0A = (int)floorf(zA); int z1A = min(z0A + 1, 47);
        int y0A = (int)floorf(yA); int y1A = min(y0A + 1, 47);
        float wz1A = zA - (float)z0A, wz0A = (float)z1A - zA;
        float wy1A = yA - (float)y0A, wy0A = (float)y1A - yA;
        float w00A = wz0A * wy0A * wxA, w01A = wz0A * wy1A * wxA;
        float w10A = wz1A * wy0A * wxA, w11A = wz1A * wy1A * wxA;
        int b00A = ((z0A * 48 + y0A) * 4) * 48 + xiA;
        int b01A = ((z0A * 48 + y1A) * 4) * 48 + xiA;
        int b10A = ((z1A * 48 + y0A) * 4) * 48 + xiA;
        int b11A = ((z1A * 48 + y1A) * 4) * 48 + xiA;

        float zB = fminf(fmaxf((float)dB + s_cz[k][tid + 128], 0.f), 47.f);
        float yB = fminf(fmaxf((float)wB + s_cy[k][tid + 128], 0.f), 47.f);
        int xiB = max(0, min(hB + k - 4, 47));
        float wxB = (xiB == 47) ? 0.f : 1.f;
        int z0B = (int)floorf(zB); int z1B = min(z0B + 1, 47);
        int y0B = (int)floorf(yB); int y1B = min(y0B + 1, 47);
        float wz1B = zB - (float)z0B, wz0B = (float)z1B - zB;
        float wy1B = yB - (float)y0B, wy0B = (float)y1B - yB;
        float w00B = wz0B * wy0B * wxB, w01B = wz0B * wy1B * wxB;
        float w10B = wz1B * wy0B * wxB, w11B = wz1B * wy1B * wxB;
        int b00B = ((z0B * 48 + y0B) * 4) * 48 + xiB;
        int b01B = ((z0B * 48 + y1B) * 4) * 48 + xiB;
        int b10B = ((z1B * 48 + y0B) * 4) * 48 + xiB;
        int b11B = ((z1B * 48 + y1B) * 4) * 48 + xiB;

#pragma unroll
        for (int c4 = 0; c4 < 4; c4++) {
            int off = c4 * 48;
            float4 vA0 = g_xl[b00A + off], vA1 = g_xl[b01A + off];
            float4 vA2 = g_xl[b10A + off], vA3 = g_xl[b11A + off];
            float4 vB0 = g_xl[b00B + off], vB1 = g_xl[b01B + off];
            float4 vB2 = g_xl[b10B + off], vB3 = g_xl[b11B + off];

            float sA[4], sB[4];
            sA[0] = w00A*vA0.x + w01A*vA1.x + w10A*vA2.x + w11A*vA3.x;
            sA[1] = w00A*vA0.y + w01A*vA1.y + w10A*vA2.y + w11A*vA3.y;
            sA[2] = w00A*vA0.z + w01A*vA1.z + w10A*vA2.z + w11A*vA3.z;
            sA[3] = w00A*vA0.w + w01A*vA1.w + w10A*vA2.w + w11A*vA3.w;
            sB[0] = w00B*vB0.x + w01B*vB1.x + w10B*vB2.x + w11B*vB3.x;
            sB[1] = w00B*vB0.y + w01B*vB1.y + w10B*vB2.y + w11B*vB3.y;
            sB[2] = w00B*vB0.z + w01B*vB1.z + w10B*vB2.z + w11B*vB3.z;
            sB[3] = w00B*vB0.w + w01B*vB1.w + w10B*vB2.w + w11B*vB3.w;

#pragma unroll
            for (int j = 0; j < 4; j++) {
                int ci = c4 * 4 + j;
                const float4* wp4 = reinterpret_cast<const float4*>(&s_dw[(ci * 9 + k) * 32]);
                float svA = sA[j], svB = sB[j];
#pragma unroll
                for (int q8 = 0; q8 < 8; q8++) {
                    float4 wv = wp4[q8];
                    accA[q8 * 4 + 0] += svA * wv.x;
                    accA[q8 * 4 + 1] += svA * wv.y;
                    accA[q8 * 4 + 2] += svA * wv.z;
                    accA[q8 * 4 + 3] += svA * wv.w;
                    accB[q8 * 4 + 0] += svB * wv.x;
                    accB[q8 * 4 + 1] += svB * wv.y;
                    accB[q8 * 4 + 2] += svB * wv.z;
                    accB[q8 * 4 + 3] += svB * wv.w;
                }
            }
        }
    }

#pragma unroll
    for (int co = 0; co < 32; co++) {
        g_pre[(size_t)co * VV + voxA] = accA[co];
        g_pre[(size_t)co * VV + voxB] = accB[co];
    }
}

// ---------------- groupnorm partials + fused last-block stats -------------------
__global__ void gsum_k() {
    int g = blockIdx.y;
    const float4* p = reinterpret_cast<const float4*>(g_pre + (size_t)g * 4 * VV);
    const int n4 = 4 * VV / 4;
    double s = 0.0, q = 0.0;
    for (int i = blockIdx.x * 256 + threadIdx.x; i < n4; i += 96 * 256) {
        float4 v = p[i];
        s += (double)v.x + (double)v.y + (double)v.z + (double)v.w;
        q += (double)v.x * v.x + (double)v.y * v.y + (double)v.z * v.z + (double)v.w * v.w;
    }
    __shared__ double sh[2][256];
    sh[0][threadIdx.x] = s; sh[1][threadIdx.x] = q;
    __syncthreads();
    for (int st = 128; st > 0; st >>= 1) {
        if (threadIdx.x < st) {
            sh[0][threadIdx.x] += sh[0][threadIdx.x + st];
            sh[1][threadIdx.x] += sh[1][threadIdx.x + st];
        }
        __syncthreads();
    }
    __shared__ bool is_last;
    if (threadIdx.x == 0) {
        g_part[(g * 96 + blockIdx.x) * 2]     = sh[0][0];
        g_part[(g * 96 + blockIdx.x) * 2 + 1] = sh[1][0];
        __threadfence();
        unsigned int prev = atomicAdd(&g_done, 1u);
        is_last = (prev == 96u * 8u - 1u);
    }
    __syncthreads();
    if (is_last && threadIdx.x < 8) {
        int gg = threadIdx.x;
        double S = 0.0, Q = 0.0;
        for (int b = 0; b < 96; b++) {
            S += g_part[(gg * 96 + b) * 2];
            Q += g_part[(gg * 96 + b) * 2 + 1];
        }
        double n   = 4.0 * (double)VV;
        double mu  = S / n;
        double var = Q / n - mu * mu;
        g_mean[gg] = (float)mu;
        g_rstd[gg] = (float)(1.0 / sqrt(var + 1e-5));
    }
}

// ---------------- groupnorm apply + relu (float4) ------------------------------
__global__ void finalize_k(const float* __restrict__ gn_g,
                           const float* __restrict__ gn_b,
                           float* __restrict__ out) {
    int i = blockIdx.x * 256 + threadIdx.x;
    int c = i / (VV / 4);
    int g = c >> 2;
    float a = g_rstd[g] * gn_g[c];
    float b = gn_b[c] - g_mean[g] * a;
    float4 v = reinterpret_cast<const float4*>(g_pre)[i];
    v.x = fmaxf(v.x * a + b, 0.f);
    v.y = fmaxf(v.y * a + b, 0.f);
    v.z = fmaxf(v.z * a + b, 0.f);
    v.w = fmaxf(v.w * a + b, 0.f);
    reinterpret_cast<float4*>(out)[i] = v;
}

// ---------------- launch --------------------------------------------------------
extern "C" void kernel_launch(void* const* d_in, const int* in_sizes, int n_in,
                              void* d_out, int out_size) {
    const float* x    = (const float*)d_in[0];
    const float* ow   = (const float*)d_in[1];
    const float* ob   = (const float*)d_in[2];
    const float* bn_g = (const float*)d_in[3];
    const float* bn_b = (const float*)d_in[4];
    const float* bn_m = (const float*)d_in[5];
    const float* bn_v = (const float*)d_in[6];
    const float* dw   = (const float*)d_in[7];
    const float* db   = (const float*)d_in[8];
    const float* gn_g = (const float*)d_in[9];
    const float* gn_b = (const float*)d_in[10];
    float* out = (float*)d_out;

    init_k<<<1, 32>>>();                    // idx 0
    init_k<<<1, 32>>>();                    // idx 1
    transpose_k<<<VV / 128, 128>>>(x);      // idx 2
    offset_conv_k<<<dim3(48, 12), dim3(24, 6)>>>(x, ow, ob, bn_g, bn_b, bn_m, bn_v); // idx 3 <- ncu
    dsc_k<<<VV / 256, 128>>>(dw, db);       // idx 4
    gsum_k<<<dim3(96, 8), 256>>>();         // idx 5
    finalize_k<<<(32 * VV / 4) / 256, 256>>>(gn_g, gn_b, out);  // idx 6
}

// round 16
// speedup vs baseline: 1.6839x; 1.6839x over previous
#include <cuda_runtime.h>
#include <math.h>

#define VV (48*48*48)          // 110592 voxels
#define EPSF 1e-5f

// ---------------- scratch (static device globals; no allocation) ----------------
__device__ float4 g_xl[(size_t)VV * 4];     // x as [z][y][c4][x] float4   (7 MB)
__device__ float  g_off[(size_t)18 * VV];   // offset conv out (18 ch)    (8 MB)
__device__ float  g_pre[(size_t)32 * VV];   // pre-groupnorm conv out     (14 MB)
__device__ double g_part[8 * 96 * 2];       // per-(group, block) partials
__device__ float  g_mean[8], g_rstd[8];
__device__ unsigned int g_done;             // gsum completion counter

__global__ void init_k() {
    if (threadIdx.x == 0) g_done = 0u;
    if (threadIdx.x < 8) { g_mean[threadIdx.x] = 0.f; g_rstd[threadIdx.x] = 0.f; }
}

// ---------------- transpose x -> [z][y][c4][x] float4 ----------------
__global__ void transpose_k(const float* __restrict__ x) {
    int vox = blockIdx.x * 128 + threadIdx.x;
    if (vox >= VV) return;
    float t[16];
#pragma unroll
    for (int ci = 0; ci < 16; ci++) t[ci] = x[(size_t)ci * VV + vox];
    int hx = vox % 48;
    int r  = vox / 48;
    int wy = r % 48;
    int dz = r / 48;
    int base = ((dz * 48 + wy) * 4) * 48 + hx;
    g_xl[base      ] = make_float4(t[0],  t[1],  t[2],  t[3]);
    g_xl[base + 48 ] = make_float4(t[4],  t[5],  t[6],  t[7]);
    g_xl[base + 96 ] = make_float4(t[8],  t[9],  t[10], t[11]);
    g_xl[base + 144] = make_float4(t[12], t[13], t[14], t[15]);
}

// ---------------- offset conv (exact R11 config: 82us, local optimum) -----------
__global__ __launch_bounds__(288, 3) void offset_conv_k(const float* __restrict__ x,
                              const float* __restrict__ ow,
                              const float* __restrict__ ob,
                              const float* __restrict__ bn_g,
                              const float* __restrict__ bn_b,
                              const float* __restrict__ bn_m,
                              const float* __restrict__ bn_v) {
    __shared__ float sx[8][6][3][50];   // 28.8KB
    __shared__ float sw[3888];          // 15.5KB

    int w  = blockIdx.x, d0 = blockIdx.y * 4;
    int tid = threadIdx.y * 48 + threadIdx.x;
    int h  = threadIdx.x;
    int co0 = threadIdx.y * 3;

    float acc[3][4];
#pragma unroll
    for (int j = 0; j < 3; j++)
#pragma unroll
        for (int i = 0; i < 4; i++) acc[j][i] = 0.f;

    for (int p = 0; p < 2; p++) {
        __syncthreads();
        for (int e = tid; e < 7200; e += 288) {
            int ci = e / 900, r = e % 900;
            int pl = r / 150; r %= 150;
            int dy = r / 50, hh = r % 50;
            int z = d0 + pl - 1, y = w + dy - 1, xx = hh - 1;
            float v = 0.f;
            if ((unsigned)z < 48u && (unsigned)y < 48u && (unsigned)xx < 48u)
                v = x[(size_t)(ci + 8 * p) * VV + ((size_t)z * 48 + y) * 48 + xx];
            sx[ci][pl][dy][hh] = v;
        }
        for (int e = tid; e < 3888; e += 288) {
            int co = e / 216, r = e % 216;
            int ci = r / 27, t = r % 27;
            sw[e] = ow[(size_t)(co * 16 + ci + 8 * p) * 27 + t];
        }
        __syncthreads();

#pragma unroll
        for (int ci = 0; ci < 8; ci++) {
#pragma unroll
            for (int dy = 0; dy < 3; dy++) {
                float v[6][3];
#pragma unroll
                for (int pl = 0; pl < 6; pl++)
#pragma unroll
                    for (int t = 0; t < 3; t++)
                        v[pl][t] = sx[ci][pl][dy][h + t];
#pragma unroll
                for (int j = 0; j < 3; j++) {
                    const float* wp = &sw[((co0 + j) * 8 + ci) * 27 + dy * 3];
#pragma unroll
                    for (int dz = 0; dz < 3; dz++) {
#pragma unroll
                        for (int t = 0; t < 3; t++) {
                            float wv = wp[dz * 9 + t];
#pragma unroll
                            for (int i = 0; i < 4; i++)
                                acc[j][i] += v[i + dz][t] * wv;
                        }
                    }
                }
            }
        }
    }

#pragma unroll
    for (int j = 0; j < 3; j++) {
        int c = co0 + j;
        float al = bn_g[c] * rsqrtf(bn_v[c] + EPSF);
        float sh = ob[c] - bn_m[c];
#pragma unroll
        for (int i = 0; i < 4; i++) {
            int vo = (((size_t)(d0 + i) * 48 + w) * 48) + h;
            g_off[(size_t)c * VV + vo] = tanhf((acc[j][i] + sh) * al + bn_b[c]);
        }
    }
}

// ---------------- dsc step: one k for both voxels ------------------------------
__device__ __forceinline__ void dsc_step(int k,
        int hA, int wA, int dA, float czA, float cyA,
        int hB, int wB, int dB, float czB, float cyB,
        const float* s_dw, float* accA, float* accB) {
    float zA = fminf(fmaxf((float)dA + czA, 0.f), 47.f);
    float yA = fminf(fmaxf((float)wA + cyA, 0.f), 47.f);
    int xiA = max(0, min(hA + k - 4, 47));
    float wxA = (xiA == 47) ? 0.f : 1.f;
    int z0A = (int)floorf(zA); int z1A = min(z0A + 1, 47);
    int y0A = (int)floorf(yA); int y1A = min(y0A + 1, 47);
    float wz1A = zA - (float)z0A, wz0A = (float)z1A - zA;
    float wy1A = yA - (float)y0A, wy0A = (float)y1A - yA;
    float w00A = wz0A * wy0A * wxA, w01A = wz0A * wy1A * wxA;
    float w10A = wz1A * wy0A * wxA, w11A = wz1A * wy1A * wxA;
    int b00A = ((z0A * 48 + y0A) * 4) * 48 + xiA;
    int b01A = ((z0A * 48 + y1A) * 4) * 48 + xiA;
    int b10A = ((z1A * 48 + y0A) * 4) * 48 + xiA;
    int b11A = ((z1A * 48 + y1A) * 4) * 48 + xiA;

    float zB = fminf(fmaxf((float)dB + czB, 0.f), 47.f);
    float yB = fminf(fmaxf((float)wB + cyB, 0.f), 47.f);
    int xiB = max(0, min(hB + k - 4, 47));
    float wxB = (xiB == 47) ? 0.f : 1.f;
    int z0B = (int)floorf(zB); int z1B = min(z0B + 1, 47);
    int y0B = (int)floorf(yB); int y1B = min(y0B + 1, 47);
    float wz1B = zB - (float)z0B, wz0B = (float)z1B - zB;
    float wy1B = yB - (float)y0B, wy0B = (float)y1B - yB;
    float w00B = wz0B * wy0B * wxB, w01B = wz0B * wy1B * wxB;
    float w10B = wz1B * wy0B * wxB, w11B = wz1B * wy1B * wxB;
    int b00B = ((z0B * 48 + y0B) * 4) * 48 + xiB;
    int b01B = ((z0B * 48 + y1B) * 4) * 48 + xiB;
    int b10B = ((z1B * 48 + y0B) * 4) * 48 + xiB;
    int b11B = ((z1B * 48 + y1B) * 4) * 48 + xiB;

#pragma unroll
    for (int c4 = 0; c4 < 4; c4++) {
        int off = c4 * 48;
        float4 vA0 = g_xl[b00A + off], vA1 = g_xl[b01A + off];
        float4 vA2 = g_xl[b10A + off], vA3 = g_xl[b11A + off];
        float4 vB0 = g_xl[b00B + off], vB1 = g_xl[b01B + off];
        float4 vB2 = g_xl[b10B + off], vB3 = g_xl[b11B + off];

        float sA[4], sB[4];
        sA[0] = w00A*vA0.x + w01A*vA1.x + w10A*vA2.x + w11A*vA3.x;
        sA[1] = w00A*vA0.y + w01A*vA1.y + w10A*vA2.y + w11A*vA3.y;
        sA[2] = w00A*vA0.z + w01A*vA1.z + w10A*vA2.z + w11A*vA3.z;
        sA[3] = w00A*vA0.w + w01A*vA1.w + w10A*vA2.w + w11A*vA3.w;
        sB[0] = w00B*vB0.x + w01B*vB1.x + w10B*vB2.x + w11B*vB3.x;
        sB[1] = w00B*vB0.y + w01B*vB1.y + w10B*vB2.y + w11B*vB3.y;
        sB[2] = w00B*vB0.z + w01B*vB1.z + w10B*vB2.z + w11B*vB3.z;
        sB[3] = w00B*vB0.w + w01B*vB1.w + w10B*vB2.w + w11B*vB3.w;

#pragma unroll
        for (int j = 0; j < 4; j++) {
            int ci = c4 * 4 + j;
            const float4* wp4 = reinterpret_cast<const float4*>(&s_dw[(ci * 9 + k) * 32]);
            float svA = sA[j], svB = sB[j];
#pragma unroll
            for (int q8 = 0; q8 < 8; q8++) {
                float4 wv = wp4[q8];
                accA[q8 * 4 + 0] += svA * wv.x;
                accA[q8 * 4 + 1] += svA * wv.y;
                accA[q8 * 4 + 2] += svA * wv.z;
                accA[q8 * 4 + 3] += svA * wv.w;
                accB[q8 * 4 + 0] += svB * wv.x;
                accB[q8 * 4 + 1] += svB * wv.y;
                accB[q8 * 4 + 2] += svB * wv.z;
                accB[q8 * 4 + 3] += svB * wv.w;
            }
        }
    }
}

// ---------------- dsc: incremental cumsum (no coord smem), 2 vox/thread ---------
// Coords carried in 4 running regs, walking k outward from center (4..8, 3..0).
// Removes 18KB smem + 36 LDS/STS per voxel + the coord barrier vs R11.
__global__ __launch_bounds__(128) void dsc_k(const float* __restrict__ dwt,
                                             const float* __restrict__ db) {
    __shared__ float s_dw[16 * 9 * 32];     // [ci][k][co]  18KB (only smem)

    int tid = threadIdx.x;
    for (int e = tid; e < 4608; e += 128) {
        int co = e / 144, r = e % 144;
        int ci = r / 9, k = r % 9;
        s_dw[(ci * 9 + k) * 32 + co] = dwt[e];
    }
    __syncthreads();

    int voxA = blockIdx.x * 256 + tid;      // 432 blocks * 256 vox = VV exactly
    int voxB = voxA + 128;
    int hA = voxA % 48, tA = voxA / 48, wA = tA % 48, dA = tA / 48;
    int hB = voxB % 48, tB = voxB / 48, wB = tB % 48, dB = tB / 48;

    float accA[32], accB[32];
#pragma unroll
    for (int co = 0; co < 32; co++) { float b = db[co]; accA[co] = b; accB[co] = b; }

    float czA, cyA, czB, cyB;

    // center: offsets are zero
    dsc_step(4, hA, wA, dA, 0.f, 0.f, hB, wB, dB, 0.f, 0.f, s_dw, accA, accB);

    // upper branch k = 5..8: cumulative from center outward
    czA = 0.f; cyA = 0.f; czB = 0.f; cyB = 0.f;
    for (int k = 5; k < 9; k++) {
        czA += g_off[(size_t)k * VV + voxA];
        cyA += g_off[(size_t)(9 + k) * VV + voxA];
        czB += g_off[(size_t)k * VV + voxB];
        cyB += g_off[(size_t)(9 + k) * VV + voxB];
        dsc_step(k, hA, wA, dA, czA, cyA, hB, wB, dB, czB, cyB, s_dw, accA, accB);
    }

    // lower branch k = 3..0: cumulative from center outward (suffix sums)
    czA = 0.f; cyA = 0.f; czB = 0.f; cyB = 0.f;
    for (int k = 3; k >= 0; k--) {
        czA += g_off[(size_t)k * VV + voxA];
        cyA += g_off[(size_t)(9 + k) * VV + voxA];
        czB += g_off[(size_t)k * VV + voxB];
        cyB += g_off[(size_t)(9 + k) * VV + voxB];
        dsc_step(k, hA, wA, dA, czA, cyA, hB, wB, dB, czB, cyB, s_dw, accA, accB);
    }

#pragma unroll
    for (int co = 0; co < 32; co++) {
        g_pre[(size_t)co * VV + voxA] = accA[co];
        g_pre[(size_t)co * VV + voxB] = accB[co];
    }
}

// ---------------- groupnorm partials + fused last-block stats -------------------
__global__ void gsum_k() {
    int g = blockIdx.y;
    const float4* p = reinterpret_cast<const float4*>(g_pre + (size_t)g * 4 * VV);
    const int n4 = 4 * VV / 4;
    double s = 0.0, q = 0.0;
    for (int i = blockIdx.x * 256 + threadIdx.x; i < n4; i += 96 * 256) {
        float4 v = p[i];
        s += (double)v.x + (double)v.y + (double)v.z + (double)v.w;
        q += (double)v.x * v.x + (double)v.y * v.y + (double)v.z * v.z + (double)v.w * v.w;
    }
    __shared__ double sh[2][256];
    sh[0][threadIdx.x] = s; sh[1][threadIdx.x] = q;
    __syncthreads();
    for (int st = 128; st > 0; st >>= 1) {
        if (threadIdx.x < st) {
            sh[0][threadIdx.x] += sh[0][threadIdx.x + st];
            sh[1][threadIdx.x] += sh[1][threadIdx.x + st];
        }
        __syncthreads();
    }
    __shared__ bool is_last;
    if (threadIdx.x == 0) {
        g_part[(g * 96 + blockIdx.x) * 2]     = sh[0][0];
        g_part[(g * 96 + blockIdx.x) * 2 + 1] = sh[1][0];
        __threadfence();
        unsigned int prev = atomicAdd(&g_done, 1u);
        is_last = (prev == 96u * 8u - 1u);
    }
    __syncthreads();
    if (is_last && threadIdx.x < 8) {
        int gg = threadIdx.x;
        double S = 0.0, Q = 0.0;
        for (int b = 0; b < 96; b++) {
            S += g_part[(gg * 96 + b) * 2];
            Q += g_part[(gg * 96 + b) * 2 + 1];
        }
        double n   = 4.0 * (double)VV;
        double mu  = S / n;
        double var = Q / n - mu * mu;
        g_mean[gg] = (float)mu;
        g_rstd[gg] = (float)(1.0 / sqrt(var + 1e-5));
    }
}

// ---------------- groupnorm apply + relu (float4) ------------------------------
__global__ void finalize_k(const float* __restrict__ gn_g,
                           const float* __restrict__ gn_b,
                           float* __restrict__ out) {
    int i = blockIdx.x * 256 + threadIdx.x;
    int c = i / (VV / 4);
    int g = c >> 2;
    float a = g_rstd[g] * gn_g[c];
    float b = gn_b[c] - g_mean[g] * a;
    float4 v = reinterpret_cast<const float4*>(g_pre)[i];
    v.x = fmaxf(v.x * a + b, 0.f);
    v.y = fmaxf(v.y * a + b, 0.f);
    v.z = fmaxf(v.z * a + b, 0.f);
    v.w = fmaxf(v.w * a + b, 0.f);
    reinterpret_cast<float4*>(out)[i] = v;
}

// ---------------- launch --------------------------------------------------------
extern "C" void kernel_launch(void* const* d_in, const int* in_sizes, int n_in,
                              void* d_out, int out_size) {
    const float* x    = (const float*)d_in[0];
    const float* ow   = (const float*)d_in[1];
    const float* ob   = (const float*)d_in[2];
    const float* bn_g = (const float*)d_in[3];
    const float* bn_b = (const float*)d_in[4];
    const float* bn_m = (const float*)d_in[5];
    const float* bn_v = (const float*)d_in[6];
    const float* dw   = (const float*)d_in[7];
    const float* db   = (const float*)d_in[8];
    const float* gn_g = (const float*)d_in[9];
    const float* gn_b = (const float*)d_in[10];
    float* out = (float*)d_out;

    init_k<<<1, 32>>>();                    // idx 0
    transpose_k<<<VV / 128, 128>>>(x);      // idx 1
    offset_conv_k<<<dim3(48, 12), dim3(48, 6)>>>(x, ow, ob, bn_g, bn_b, bn_m, bn_v); // idx 2
    dsc_k<<<VV / 256, 128>>>(dw, db);       // idx 3 <- ncu target
    gsum_k<<<dim3(96, 8), 256>>>();         // idx 4
    finalize_k<<<(32 * VV / 4) / 256, 256>>>(gn_g, gn_b, out);  // idx 5
}

// round 17
// speedup vs baseline: 2.0471x; 1.2157x over previous
#include <cuda_runtime.h>
#include <math.h>

#define VV (48*48*48)          // 110592 voxels
#define NBLK 432               // dsc grid size
#define EPSF 1e-5f

// ---------------- scratch (static device globals; no allocation) ----------------
__device__ float4 g_xl[(size_t)VV * 4];     // x as [z][y][c4][x] float4   (7 MB)
__device__ float  g_off[(size_t)18 * VV];   // offset conv out (18 ch)    (8 MB)
__device__ float  g_pre[(size_t)32 * VV];   // pre-groupnorm conv out     (14 MB)
__device__ double g_part[8 * NBLK * 2];     // per-(group, dsc-block) partials
__device__ float  g_mean[8], g_rstd[8];
__device__ unsigned int g_done;             // dsc completion counter

__global__ void init_k() {
    if (threadIdx.x == 0) g_done = 0u;
    if (threadIdx.x < 8) { g_mean[threadIdx.x] = 0.f; g_rstd[threadIdx.x] = 0.f; }
}

// ---------------- transpose x -> [z][y][c4][x] float4 ----------------
__global__ void transpose_k(const float* __restrict__ x) {
    int vox = blockIdx.x * 128 + threadIdx.x;
    if (vox >= VV) return;
    float t[16];
#pragma unroll
    for (int ci = 0; ci < 16; ci++) t[ci] = x[(size_t)ci * VV + vox];
    int hx = vox % 48;
    int r  = vox / 48;
    int wy = r % 48;
    int dz = r / 48;
    int base = ((dz * 48 + wy) * 4) * 48 + hx;
    g_xl[base      ] = make_float4(t[0],  t[1],  t[2],  t[3]);
    g_xl[base + 48 ] = make_float4(t[4],  t[5],  t[6],  t[7]);
    g_xl[base + 96 ] = make_float4(t[8],  t[9],  t[10], t[11]);
    g_xl[base + 144] = make_float4(t[12], t[13], t[14], t[15]);
}

// ---------------- offset conv (R11 config: 82us, local optimum) -----------------
__global__ __launch_bounds__(288, 3) void offset_conv_k(const float* __restrict__ x,
                              const float* __restrict__ ow,
                              const float* __restrict__ ob,
                              const float* __restrict__ bn_g,
                              const float* __restrict__ bn_b,
                              const float* __restrict__ bn_m,
                              const float* __restrict__ bn_v) {
    __shared__ float sx[8][6][3][50];   // 28.8KB
    __shared__ float sw[3888];          // 15.5KB

    int w  = blockIdx.x, d0 = blockIdx.y * 4;
    int tid = threadIdx.y * 48 + threadIdx.x;
    int h  = threadIdx.x;
    int co0 = threadIdx.y * 3;

    float acc[3][4];
#pragma unroll
    for (int j = 0; j < 3; j++)
#pragma unroll
        for (int i = 0; i < 4; i++) acc[j][i] = 0.f;

    for (int p = 0; p < 2; p++) {
        __syncthreads();
        for (int e = tid; e < 7200; e += 288) {
            int ci = e / 900, r = e % 900;
            int pl = r / 150; r %= 150;
            int dy = r / 50, hh = r % 50;
            int z = d0 + pl - 1, y = w + dy - 1, xx = hh - 1;
            float v = 0.f;
            if ((unsigned)z < 48u && (unsigned)y < 48u && (unsigned)xx < 48u)
                v = x[(size_t)(ci + 8 * p) * VV + ((size_t)z * 48 + y) * 48 + xx];
            sx[ci][pl][dy][hh] = v;
        }
        for (int e = tid; e < 3888; e += 288) {
            int co = e / 216, r = e % 216;
            int ci = r / 27, t = r % 27;
            sw[e] = ow[(size_t)(co * 16 + ci + 8 * p) * 27 + t];
        }
        __syncthreads();

#pragma unroll
        for (int ci = 0; ci < 8; ci++) {
#pragma unroll
            for (int dy = 0; dy < 3; dy++) {
                float v[6][3];
#pragma unroll
                for (int pl = 0; pl < 6; pl++)
#pragma unroll
                    for (int t = 0; t < 3; t++)
                        v[pl][t] = sx[ci][pl][dy][h + t];
#pragma unroll
                for (int j = 0; j < 3; j++) {
                    const float* wp = &sw[((co0 + j) * 8 + ci) * 27 + dy * 3];
#pragma unroll
                    for (int dz = 0; dz < 3; dz++) {
#pragma unroll
                        for (int t = 0; t < 3; t++) {
                            float wv = wp[dz * 9 + t];
#pragma unroll
                            for (int i = 0; i < 4; i++)
                                acc[j][i] += v[i + dz][t] * wv;
                        }
                    }
                }
            }
        }
    }

#pragma unroll
    for (int j = 0; j < 3; j++) {
        int c = co0 + j;
        float al = bn_g[c] * rsqrtf(bn_v[c] + EPSF);
        float sh = ob[c] - bn_m[c];
#pragma unroll
        for (int i = 0; i < 4; i++) {
            int vo = (((size_t)(d0 + i) * 48 + w) * 48) + h;
            g_off[(size_t)c * VV + vo] = tanhf((acc[j][i] + sh) * al + bn_b[c]);
        }
    }
}

// ---------------- dsc (R11 mainloop) + fused groupnorm partials -----------------
__global__ __launch_bounds__(128) void dsc_k(const float* __restrict__ dwt,
                                             const float* __restrict__ db) {
    __shared__ float s_dw[16 * 9 * 32];     // [ci][k][co]  18KB
    __shared__ float s_cz[9][256];          // 9KB
    __shared__ float s_cy[9][256];          // 9KB
    __shared__ double s_red[2][8][4];       // [s|q][group][warp] 512B

    int tid = threadIdx.x;
    for (int e = tid; e < 4608; e += 128) {
        int co = e / 144, r = e % 144;
        int ci = r / 9, k = r % 9;
        s_dw[(ci * 9 + k) * 32 + co] = dwt[e];
    }

    int voxA = blockIdx.x * 256 + tid;      // 432 blocks * 256 vox = VV exactly

    for (int half = 0; half < 2; half++) {
        int vox = voxA + half * 128;
        int col = tid + half * 128;
        float o[9];
#pragma unroll
        for (int k = 0; k < 9; k++) o[k] = g_off[(size_t)k * VV + vox];
        float c3 = o[3], c2 = o[2] + c3, c1 = o[1] + c2, c0 = o[0] + c1;
        float c5 = o[5], c6 = o[6] + c5, c7 = o[7] + c6, c8 = o[8] + c7;
        s_cz[0][col] = c0; s_cz[1][col] = c1; s_cz[2][col] = c2; s_cz[3][col] = c3;
        s_cz[4][col] = 0.f;
        s_cz[5][col] = c5; s_cz[6][col] = c6; s_cz[7][col] = c7; s_cz[8][col] = c8;
#pragma unroll
        for (int k = 0; k < 9; k++) o[k] = g_off[(size_t)(9 + k) * VV + vox];
        c3 = o[3]; c2 = o[2] + c3; c1 = o[1] + c2; c0 = o[0] + c1;
        c5 = o[5]; c6 = o[6] + c5; c7 = o[7] + c6; c8 = o[8] + c7;
        s_cy[0][col] = c0; s_cy[1][col] = c1; s_cy[2][col] = c2; s_cy[3][col] = c3;
        s_cy[4][col] = 0.f;
        s_cy[5][col] = c5; s_cy[6][col] = c6; s_cy[7][col] = c7; s_cy[8][col] = c8;
    }
    __syncthreads();

    int voxB = voxA + 128;
    int hA = voxA % 48, tA = voxA / 48, wA = tA % 48, dA = tA / 48;
    int hB = voxB % 48, tB = voxB / 48, wB = tB % 48, dB = tB / 48;

    float accA[32], accB[32];
#pragma unroll
    for (int co = 0; co < 32; co++) { float b = db[co]; accA[co] = b; accB[co] = b; }

    for (int k = 0; k < 9; k++) {
        float zA = fminf(fmaxf((float)dA + s_cz[k][tid], 0.f), 47.f);
        float yA = fminf(fmaxf((float)wA + s_cy[k][tid], 0.f), 47.f);
        int xiA = max(0, min(hA + k - 4, 47));
        float wxA = (xiA == 47) ? 0.f : 1.f;
        int z0A = (int)floorf(zA); int z1A = min(z0A + 1, 47);
        int y0A = (int)floorf(yA); int y1A = min(y0A + 1, 47);
        float wz1A = zA - (float)z0A, wz0A = (float)z1A - zA;
        float wy1A = yA - (float)y0A, wy0A = (float)y1A - yA;
        float w00A = wz0A * wy0A * wxA, w01A = wz0A * wy1A * wxA;
        float w10A = wz1A * wy0A * wxA, w11A = wz1A * wy1A * wxA;
        int b00A = ((z0A * 48 + y0A) * 4) * 48 + xiA;
        int b01A = ((z0A * 48 + y1A) * 4) * 48 + xiA;
        int b10A = ((z1A * 48 + y0A) * 4) * 48 + xiA;
        int b11A = ((z1A * 48 + y1A) * 4) * 48 + xiA;

        float zB = fminf(fmaxf((float)dB + s_cz[k][tid + 128], 0.f), 47.f);
        float yB = fminf(fmaxf((float)wB + s_cy[k][tid + 128], 0.f), 47.f);
        int xiB = max(0, min(hB + k - 4, 47));
        float wxB = (xiB == 47) ? 0.f : 1.f;
        int z0B = (int)floorf(zB); int z1B = min(z0B + 1, 47);
        int y0B = (int)floorf(yB); int y1B = min(y0B + 1, 47);
        float wz1B = zB - (float)z0B, wz0B = (float)z1B - zB;
        float wy1B = yB - (float)y0B, wy0B = (float)y1B - yB;
        float w00B = wz0B * wy0B * wxB, w01B = wz0B * wy1B * wxB;
        float w10B = wz1B * wy0B * wxB, w11B = wz1B * wy1B * wxB;
        int b00B = ((z0B * 48 + y0B) * 4) * 48 + xiB;
        int b01B = ((z0B * 48 + y1B) * 4) * 48 + xiB;
        int b10B = ((z1B * 48 + y0B) * 4) * 48 + xiB;
        int b11B = ((z1B * 48 + y1B) * 4) * 48 + xiB;

#pragma unroll
        for (int c4 = 0; c4 < 4; c4++) {
            int off = c4 * 48;
            float4 vA0 = g_xl[b00A + off], vA1 = g_xl[b01A + off];
            float4 vA2 = g_xl[b10A + off], vA3 = g_xl[b11A + off];
            float4 vB0 = g_xl[b00B + off], vB1 = g_xl[b01B + off];
            float4 vB2 = g_xl[b10B + off], vB3 = g_xl[b11B + off];

            float sA[4], sB[4];
            sA[0] = w00A*vA0.x + w01A*vA1.x + w10A*vA2.x + w11A*vA3.x;
            sA[1] = w00A*vA0.y + w01A*vA1.y + w10A*vA2.y + w11A*vA3.y;
            sA[2] = w00A*vA0.z + w01A*vA1.z + w10A*vA2.z + w11A*vA3.z;
            sA[3] = w00A*vA0.w + w01A*vA1.w + w10A*vA2.w + w11A*vA3.w;
            sB[0] = w00B*vB0.x + w01B*vB1.x + w10B*vB2.x + w11B*vB3.x;
            sB[1] = w00B*vB0.y + w01B*vB1.y + w10B*vB2.y + w11B*vB3.y;
            sB[2] = w00B*vB0.z + w01B*vB1.z + w10B*vB2.z + w11B*vB3.z;
            sB[3] = w00B*vB0.w + w01B*vB1.w + w10B*vB2.w + w11B*vB3.w;

#pragma unroll
            for (int j = 0; j < 4; j++) {
                int ci = c4 * 4 + j;
                const float4* wp4 = reinterpret_cast<const float4*>(&s_dw[(ci * 9 + k) * 32]);
                float svA = sA[j], svB = sB[j];
#pragma unroll
                for (int q8 = 0; q8 < 8; q8++) {
                    float4 wv = wp4[q8];
                    accA[q8 * 4 + 0] += svA * wv.x;
                    accA[q8 * 4 + 1] += svA * wv.y;
                    accA[q8 * 4 + 2] += svA * wv.z;
                    accA[q8 * 4 + 3] += svA * wv.w;
                    accB[q8 * 4 + 0] += svB * wv.x;
                    accB[q8 * 4 + 1] += svB * wv.y;
                    accB[q8 * 4 + 2] += svB * wv.z;
                    accB[q8 * 4 + 3] += svB * wv.w;
                }
            }
        }
    }

#pragma unroll
    for (int co = 0; co < 32; co++) {
        g_pre[(size_t)co * VV + voxA] = accA[co];
        g_pre[(size_t)co * VV + voxB] = accB[co];
    }

    // ---- fused groupnorm partials: values are already in registers ----
    int lane = tid & 31, wrp = tid >> 5;
#pragma unroll
    for (int g = 0; g < 8; g++) {
        float s0 = (accA[4*g] + accA[4*g+1]) + (accA[4*g+2] + accA[4*g+3])
                 + (accB[4*g] + accB[4*g+1]) + (accB[4*g+2] + accB[4*g+3]);
        float q0 = accA[4*g]*accA[4*g] + accA[4*g+1]*accA[4*g+1]
                 + accA[4*g+2]*accA[4*g+2] + accA[4*g+3]*accA[4*g+3]
                 + accB[4*g]*accB[4*g] + accB[4*g+1]*accB[4*g+1]
                 + accB[4*g+2]*accB[4*g+2] + accB[4*g+3]*accB[4*g+3];
        double s = (double)s0, q = (double)q0;
#pragma unroll
        for (int off = 16; off > 0; off >>= 1) {
            s += __shfl_down_sync(0xffffffffu, s, off);
            q += __shfl_down_sync(0xffffffffu, q, off);
        }
        if (lane == 0) { s_red[0][g][wrp] = s; s_red[1][g][wrp] = q; }
    }
    __syncthreads();
    __shared__ bool is_last;
    if (tid < 8) {
        int g = tid;
        double S = (s_red[0][g][0] + s_red[0][g][1]) + (s_red[0][g][2] + s_red[0][g][3]);
        double Q = (s_red[1][g][0] + s_red[1][g][1]) + (s_red[1][g][2] + s_red[1][g][3]);
        g_part[(g * NBLK + blockIdx.x) * 2]     = S;
        g_part[(g * NBLK + blockIdx.x) * 2 + 1] = Q;
    }
    __syncthreads();
    if (tid == 0) {
        __threadfence();
        unsigned int prev = atomicAdd(&g_done, 1u);
        is_last = (prev == (unsigned)NBLK - 1u);
    }
    __syncthreads();
    if (is_last) {
        // 4 warps x 2 passes cover the 8 groups; lane-strided + shfl tree (fixed order)
        for (int pass = 0; pass < 2; pass++) {
            int g = (tid >> 5) + 4 * pass;
            double S = 0.0, Q = 0.0;
            for (int b = lane; b < NBLK; b += 32) {
                S += g_part[(g * NBLK + b) * 2];
                Q += g_part[(g * NBLK + b) * 2 + 1];
            }
#pragma unroll
            for (int off = 16; off > 0; off >>= 1) {
                S += __shfl_down_sync(0xffffffffu, S, off);
                Q += __shfl_down_sync(0xffffffffu, Q, off);
            }
            if (lane == 0) {
                double n   = 4.0 * (double)VV;
                double mu  = S / n;
                double var = Q / n - mu * mu;
                g_mean[g] = (float)mu;
                g_rstd[g] = (float)(1.0 / sqrt(var + 1e-5));
            }
        }
    }
}

// ---------------- groupnorm apply + relu (float4) ------------------------------
__global__ void finalize_k(const float* __restrict__ gn_g,
                           const float* __restrict__ gn_b,
                           float* __restrict__ out) {
    int i = blockIdx.x * 256 + threadIdx.x;
    int c = i / (VV / 4);
    int g = c >> 2;
    float a = g_rstd[g] * gn_g[c];
    float b = gn_b[c] - g_mean[g] * a;
    float4 v = reinterpret_cast<const float4*>(g_pre)[i];
    v.x = fmaxf(v.x * a + b, 0.f);
    v.y = fmaxf(v.y * a + b, 0.f);
    v.z = fmaxf(v.z * a + b, 0.f);
    v.w = fmaxf(v.w * a + b, 0.f);
    reinterpret_cast<float4*>(out)[i] = v;
}

// ---------------- launch --------------------------------------------------------
extern "C" void kernel_launch(void* const* d_in, const int* in_sizes, int n_in,
                              void* d_out, int out_size) {
    const float* x    = (const float*)d_in[0];
    const float* ow   = (const float*)d_in[1];
    const float* ob   = (const float*)d_in[2];
    const float* bn_g = (const float*)d_in[3];
    const float* bn_b = (const float*)d_in[4];
    const float* bn_m = (const float*)d_in[5];
    const float* bn_v = (const float*)d_in[6];
    const float* dw   = (const float*)d_in[7];
    const float* db   = (const float*)d_in[8];
    const float* gn_g = (const float*)d_in[9];
    const float* gn_b = (const float*)d_in[10];
    float* out = (float*)d_out;

    init_k<<<1, 32>>>();                    // idx 0  (resets g_done each replay)
    transpose_k<<<VV / 128, 128>>>(x);      // idx 1
    offset_conv_k<<<dim3(48, 12), dim3(48, 6)>>>(x, ow, ob, bn_g, bn_b, bn_m, bn_v); // idx 2
    dsc_k<<<NBLK, 128>>>(dw, db);           // idx 3 <- ncu target (gsum fused)
    finalize_k<<<(32 * VV / 4) / 256, 256>>>(gn_g, gn_b, out);  // idx 4
}